// round 15
// baseline (speedup 1.0000x reference)
#include <cuda_runtime.h>
#include <cuda_bf16.h>

// Problem constants (fixed by the reference)
#define BATCH 16
#define MCTRL 64
#define NCTRL 64
#define DEG   3
#define LKNOT 68                // M + P + 1
#define NSPAN (LKNOT - 2*DEG)   // 62 candidate spans
#define OUTU  256
#define OUTV  256
#define U_PER 8                 // u samples per block
#define V_PER 128               // v samples per block (half of OUTV)

// Fully fused kernel, v-split for occupancy WITHOUT redundant basis work.
// Grid: (OUTU/U_PER * 2, BATCH) = (64, 16) = 1024 blocks x 256 threads.
// blockIdx.x: u-tile = x>>1, v-half = x&1.
//
//   1. Warp 0: load 68 knots, pure-shfl inclusive scan, normalize -> K[].
//      (Nu == Nv and uspan == vspan: the reference builds V from knot_u;
//       u/v linspaces + degrees are identical -> one table serves both axes.)
//   2. Each thread: compute its TWO fold tasks' u-spans (cheap binary
//      searches), issue all 8 LDG.128 control-point prefetches (MLP=8).
//   3. Basis (overlapped with the LDGs): threads 0..127 compute the v-basis
//      for v = v0 + t and publish to smem; threads 128..135 compute the 8
//      u-bases. Total basis work per block: 136 samples (not 256).
//   4. Barrier; fold both tasks into stmp with the prefetched data; barrier.
//   5. Stage B: thread t evaluates v = v0 + (t&127) for 4 u's
//      (u-group = (t>>7)*4): 4 LDS.128 + 12 FMA + 3 streaming STG per point.
//
// Span-search correctness: the reference predicate (tv - K[s+DEG]) > 1e-8 is
// prefix-true in s (K monotone non-decreasing; fp subtract with a fixed
// minuend is monotone), so argmin-with-first-tie == prefix-count - 1. The
// binary search probes the identical fp expression -> bit-equal span.
// Cox-de Boor uses __fdividef (2-ulp) -- ~1e-6 impact vs 1e-3 tolerance.

__device__ __forceinline__ int find_cnt(const float* __restrict__ K, float tv) {
    int cnt = 0;
    #pragma unroll
    for (int s = 32; s; s >>= 1) {
        const int ns = cnt + s;
        if (ns <= NSPAN && ((tv - K[ns - 1 + DEG]) > 1e-8f)) cnt = ns;
    }
    return cnt;
}

__device__ __forceinline__ float4 cox_de_boor(const float* __restrict__ K,
                                              float tv, int span) {
    float Nb[DEG + 1];
    Nb[0] = 1.f;
    #pragma unroll
    for (int k = 1; k <= DEG; k++) {
        float saved = 0.f;
        #pragma unroll
        for (int r = 0; r < k; r++) {
            const float K1 = K[span + r + 1];
            const float K2 = K[span + 1 - k + r];
            const float denom = (K1 - tv) + (tv - K2);
            const float temp  = __fdividef(Nb[r], denom);
            Nb[r] = saved + (K1 - tv) * temp;
            saved = (tv - K2) * temp;
        }
        Nb[k] = saved;
    }
    return make_float4(Nb[0], Nb[1], Nb[2], Nb[3]);
}

__global__ void __launch_bounds__(256) surf_kernel(const float* __restrict__ ctrl,
                                                   const float* __restrict__ knot_u,
                                                   float* __restrict__ out) {
    const int ut = blockIdx.x >> 1;
    const int h  = blockIdx.x & 1;
    const int b  = blockIdx.y;
    const int t  = threadIdx.x;
    const int u0 = ut * U_PER;
    const int v0 = h * V_PER;

    __shared__ float  K[LKNOT];           // normalized knots
    __shared__ float4 sbu[U_PER];         // u bases for this block's u-tile
    __shared__ float4 sbv[V_PER];         // v bases for this block's v-half
    __shared__ int    ssv[V_PER];         // v span-bases
    __shared__ float4 stmp[U_PER][NCTRL]; // u-folded rows (8 KB)

    // ---- 1. warp-0 knot scan + normalize ----------------------------------
    if (t < 32) {
        const float* kn = knot_u + b * LKNOT;
        const int l = t;
        float a0 = kn[l];
        float a1 = kn[l + 32];
        float a2 = (l < 4) ? kn[l + 64] : 0.f;

        #pragma unroll
        for (int off = 1; off < 32; off <<= 1) {
            const float n0 = __shfl_up_sync(0xffffffffu, a0, off);
            const float n1 = __shfl_up_sync(0xffffffffu, a1, off);
            const float n2 = __shfl_up_sync(0xffffffffu, a2, off);
            if (l >= off) { a0 += n0; a1 += n1; a2 += n2; }
        }
        const float tot0  = __shfl_sync(0xffffffffu, a0, 31);
        const float tot1  = __shfl_sync(0xffffffffu, a1, 31);
        const float cs2_3 = __shfl_sync(0xffffffffu, a2, 3);   // sum of last 4
        const float c0    = __shfl_sync(0xffffffffu, a0, 0);   // cs[0]
        const float den   = (tot0 + tot1 + cs2_3) - c0;        // cs[67]-cs[0]

        K[l]      = (a0 - c0) / den;
        K[l + 32] = (tot0 + a1 - c0) / den;
        if (l < 4) K[l + 64] = (tot0 + tot1 + a2 - c0) / den;
    }
    __syncthreads();

    // linspace(1e-5, 1-1e-5, 256): start + i*step, endpoint exact.
    const float start = 1e-5f;
    const float stop  = 1.0f - 1e-5f;
    const float step  = (stop - start) / (float)(OUTU - 1);

    // ---- 2. fold-task spans (cheap) + 8-deep LDG prefetch -----------------
    const int up = t >> 6;            // 0..3  (second task: up+4)
    const int n  = t & 63;            // 0..63
    const int uA = u0 + up;
    const int uB = u0 + up + 4;

    float tA = start + (float)uA * step;
    if (uA == OUTU - 1) tA = stop;
    float tB = start + (float)uB * step;
    if (uB == OUTU - 1) tB = stop;

    const int sA = find_cnt(K, tA) - 1;    // spanA - DEG
    const int sB = find_cnt(K, tB) - 1;

    const float4* cp = reinterpret_cast<const float4*>(ctrl)
                     + (size_t)b * MCTRL * NCTRL + n;
    // All 8 loads in flight across the basis math below (MLP=8).
    const float4 a0 = cp[(sA + 0) * NCTRL];
    const float4 a1 = cp[(sA + 1) * NCTRL];
    const float4 a2 = cp[(sA + 2) * NCTRL];
    const float4 a3 = cp[(sA + 3) * NCTRL];
    const float4 b0 = cp[(sB + 0) * NCTRL];
    const float4 b1 = cp[(sB + 1) * NCTRL];
    const float4 b2 = cp[(sB + 2) * NCTRL];
    const float4 b3 = cp[(sB + 3) * NCTRL];

    // ---- 3. basis: 128 v-samples + 8 u-samples (no redundancy) ------------
    if (t < V_PER) {
        const int v = v0 + t;
        float tv = start + (float)v * step;
        if (v == OUTV - 1) tv = stop;
        const int cv = find_cnt(K, tv);
        sbv[t] = cox_de_boor(K, tv, DEG + cv - 1);
        ssv[t] = cv - 1;
    } else if (t < V_PER + U_PER) {
        const int du = t - V_PER;
        const int uu = u0 + du;
        float tu = start + (float)uu * step;
        if (uu == OUTU - 1) tu = stop;
        const int cu = find_cnt(K, tu);
        sbu[du] = cox_de_boor(K, tu, DEG + cu - 1);
    }
    __syncthreads();

    // ---- 4. fold both tasks (prefetched data now resident) ----------------
    {
        const float4 NA = sbu[up];
        const float4 NB = sbu[up + 4];

        float4 r;
        r.x = fmaf(NA.x, a0.x, fmaf(NA.y, a1.x, fmaf(NA.z, a2.x, NA.w * a3.x)));
        r.y = fmaf(NA.x, a0.y, fmaf(NA.y, a1.y, fmaf(NA.z, a2.y, NA.w * a3.y)));
        r.z = fmaf(NA.x, a0.z, fmaf(NA.y, a1.z, fmaf(NA.z, a2.z, NA.w * a3.z)));
        r.w = 0.f;
        stmp[up][n] = r;

        float4 s;
        s.x = fmaf(NB.x, b0.x, fmaf(NB.y, b1.x, fmaf(NB.z, b2.x, NB.w * b3.x)));
        s.y = fmaf(NB.x, b0.y, fmaf(NB.y, b1.y, fmaf(NB.z, b2.y, NB.w * b3.y)));
        s.z = fmaf(NB.x, b0.z, fmaf(NB.y, b1.z, fmaf(NB.z, b2.z, NB.w * b3.z)));
        s.w = 0.f;
        stmp[up + 4][n] = s;
    }
    __syncthreads();

    // ---- 5. Stage B: v = v0 + (t&127), u-group = (t>>7)*4 ------------------
    const int vi = t & (V_PER - 1);
    const int ug = (t >> 7) * 4;
    const int v  = v0 + vi;

    const float4 nv = sbv[vi];
    const int    sv = ssv[vi];

    float* op = out + (((size_t)b * OUTU + (u0 + ug)) * OUTV + v) * 3;

    #pragma unroll
    for (int w = 0; w < 4; w++) {
        const float4 c0 = stmp[ug + w][sv + 0];
        const float4 c1 = stmp[ug + w][sv + 1];
        const float4 c2 = stmp[ug + w][sv + 2];
        const float4 c3 = stmp[ug + w][sv + 3];

        const float ax = fmaf(nv.x, c0.x, fmaf(nv.y, c1.x, fmaf(nv.z, c2.x, nv.w * c3.x)));
        const float ay = fmaf(nv.x, c0.y, fmaf(nv.y, c1.y, fmaf(nv.z, c2.y, nv.w * c3.y)));
        const float az = fmaf(nv.x, c0.z, fmaf(nv.y, c1.z, fmaf(nv.z, c2.z, nv.w * c3.z)));

        float* o = op + (size_t)w * OUTV * 3;
        __stcs(o + 0, ax);   // streaming: write-once output, keep out of L1
        __stcs(o + 1, ay);
        __stcs(o + 2, az);
    }
}

// ---------------------------------------------------------------------------
// Launch. Inputs per metadata order: ctrl_pts [16,64,64,4] f32,
// knot_u [16,68] f32, knot_v [16,68] f32 (unused — the reference builds both
// directions from knot_u).
// ---------------------------------------------------------------------------
extern "C" void kernel_launch(void* const* d_in, const int* in_sizes, int n_in,
                              void* d_out, int out_size) {
    const float* ctrl   = (const float*)d_in[0];
    const float* knot_u = (const float*)d_in[1];
    float* out = (float*)d_out;

    surf_kernel<<<dim3((OUTU / U_PER) * 2, BATCH), 256>>>(ctrl, knot_u, out);
}